// round 2
// baseline (speedup 1.0000x reference)
#include <cuda_runtime.h>

#define NN  100000
#define NE  1250000
#define NP  200000
#define HIDD 64
#define IND 128
#define NB_SCAN 98   // ceil(100000/1024)

// ---------------- scratch (device globals; no allocation allowed) -------------
__device__ __align__(16) float g_h [NN * HIDD];
__device__ __align__(16) float g_h2[NN * HIDD];
__device__ __align__(16) float g_agg[NN * HIDD];
__device__ int   g_rowstart[NN + 1];
__device__ int   g_cursor[NN];      // used as deg accumulator, then fill cursor
__device__ int   g_col[NE];
__device__ int   g_bsum[NB_SCAN + 8];

// ---------------- CSR build ---------------------------------------------------
__global__ void k_zero_cursor() {
    int i = blockIdx.x * blockDim.x + threadIdx.x;
    if (i < NN) g_cursor[i] = 0;
}

__global__ void k_hist(const int* __restrict__ ei) {
    int e = blockIdx.x * blockDim.x + threadIdx.x;
    if (e < NE) {
        int d = ei[NE + e];   // dst row (int32)
        if ((unsigned)d < NN) atomicAdd(&g_cursor[d], 1);
    }
}

// block-local exclusive scan of degrees (in g_cursor) -> g_rowstart, block sums -> g_bsum
__global__ void k_scan1() {
    __shared__ int s[1024];
    int tid = threadIdx.x;
    int i = blockIdx.x * 1024 + tid;
    int v = (i < NN) ? g_cursor[i] : 0;
    s[tid] = v;
    __syncthreads();
    for (int off = 1; off < 1024; off <<= 1) {
        int t = 0;
        if (tid >= off) t = s[tid - off];
        __syncthreads();
        if (tid >= off) s[tid] += t;
        __syncthreads();
    }
    if (i < NN) g_rowstart[i] = s[tid] - v;   // exclusive
    if (tid == 1023) g_bsum[blockIdx.x] = s[1023];
}

__global__ void k_scan2() {
    __shared__ int s[NB_SCAN];
    int tid = threadIdx.x;
    if (tid < NB_SCAN) s[tid] = g_bsum[tid];
    __syncthreads();
    if (tid == 0) {
        int run = 0;
        for (int b = 0; b < NB_SCAN; b++) { int t = s[b]; s[b] = run; run += t; }
    }
    __syncthreads();
    if (tid < NB_SCAN) g_bsum[tid] = s[tid];
}

__global__ void k_scan3() {
    int i = blockIdx.x * 1024 + threadIdx.x;
    if (i < NN) {
        int r = g_rowstart[i] + g_bsum[blockIdx.x];
        g_rowstart[i] = r;
        g_cursor[i]   = r;
    }
    if (blockIdx.x == 0 && threadIdx.x == 0) g_rowstart[NN] = NE;
}

__global__ void k_fill(const int* __restrict__ ei) {
    int e = blockIdx.x * blockDim.x + threadIdx.x;
    if (e < NE) {
        int s = ei[e];
        int d = ei[NE + e];
        if ((unsigned)d < NN && (unsigned)s < NN) {
            int pos = atomicAdd(&g_cursor[d], 1);
            if ((unsigned)pos < NE) g_col[pos] = s;
        }
    }
}

// ---------------- encoder: h = relu(x @ enc_W + enc_b) ------------------------
#define ENC_NPB 64
__global__ void k_encoder(const float* __restrict__ x,
                          const float* __restrict__ W,
                          const float* __restrict__ b) {
    __shared__ float Ws[IND * HIDD];        // 32 KB
    __shared__ float bs[HIDD];
    __shared__ float xs[16][IND];           // 8 KB
    int t = threadIdx.x;                    // 256 threads
    for (int i = t; i < IND * HIDD; i += 256) Ws[i] = W[i];
    if (t < HIDD) bs[t] = b[t];
    int j = t & 63;
    int g = t >> 6;                         // 0..3, 4 nodes each -> 16 nodes/iter
    int base = blockIdx.x * ENC_NPB;
    for (int it = 0; it < ENC_NPB; it += 16) {
        __syncthreads();
        {   // stage 16 rows of x (float4)
            const float4* xsrc = (const float4*)(x + (size_t)(base + it) * IND);
            float4* xdst = (float4*)&xs[0][0];
            for (int i = t; i < 16 * IND / 4; i += 256) {
                int node = base + it + i / (IND / 4);
                xdst[i] = (node < NN) ? xsrc[i] : make_float4(0.f, 0.f, 0.f, 0.f);
            }
        }
        __syncthreads();
        int n0 = g * 4;
        float a0 = bs[j], a1 = bs[j], a2 = bs[j], a3 = bs[j];
#pragma unroll 8
        for (int k = 0; k < IND; k++) {
            float w = Ws[k * HIDD + j];
            a0 = fmaf(xs[n0 + 0][k], w, a0);
            a1 = fmaf(xs[n0 + 1][k], w, a1);
            a2 = fmaf(xs[n0 + 2][k], w, a2);
            a3 = fmaf(xs[n0 + 3][k], w, a3);
        }
        int node = base + it + n0;
        if (node + 0 < NN) g_h[(size_t)(node + 0) * HIDD + j] = fmaxf(a0, 0.f);
        if (node + 1 < NN) g_h[(size_t)(node + 1) * HIDD + j] = fmaxf(a1, 0.f);
        if (node + 2 < NN) g_h[(size_t)(node + 2) * HIDD + j] = fmaxf(a2, 0.f);
        if (node + 3 < NN) g_h[(size_t)(node + 3) * HIDD + j] = fmaxf(a3, 0.f);
    }
}

// ---------------- mean aggregation (CSR gather; warp per node) ----------------
__global__ void k_aggregate(int flip) {
    const float* __restrict__ hin = flip ? g_h2 : g_h;
    int warp = (blockIdx.x * blockDim.x + threadIdx.x) >> 5;
    int lane = threadIdx.x & 31;
    if (warp >= NN) return;
    int s0 = g_rowstart[warp];
    int s1 = g_rowstart[warp + 1];
    float a0 = 0.f, a1 = 0.f;
    int e = s0;
    for (; e + 1 < s1; e += 2) {
        int src0 = g_col[e];
        int src1 = g_col[e + 1];
        const float* r0 = hin + (size_t)src0 * HIDD;
        const float* r1 = hin + (size_t)src1 * HIDD;
        a0 += r0[lane]      + r1[lane];
        a1 += r0[lane + 32] + r1[lane + 32];
    }
    if (e < s1) {
        const float* r0 = hin + (size_t)g_col[e] * HIDD;
        a0 += r0[lane];
        a1 += r0[lane + 32];
    }
    float inv = (s1 > s0) ? 1.0f / (float)(s1 - s0) : 0.f;
    g_agg[(size_t)warp * HIDD + lane]      = a0 * inv;
    g_agg[(size_t)warp * HIDD + lane + 32] = a1 * inv;
}

// ---------------- layer update: h' = relu(agg@Wl + bl + h@Wr) -----------------
#define UPD_NPB 64
__global__ void k_update(int flip,
                         const float* __restrict__ Wl,
                         const float* __restrict__ bl,
                         const float* __restrict__ Wr) {
    const float* __restrict__ hin = flip ? g_h2 : g_h;
    float* __restrict__ hout      = flip ? g_h  : g_h2;
    __shared__ float Wls[HIDD * HIDD];      // 16 KB
    __shared__ float Wrs[HIDD * HIDD];      // 16 KB
    __shared__ float bls[HIDD];
    __shared__ float as[16][HIDD];          // 4 KB
    __shared__ float hs[16][HIDD];          // 4 KB
    int t = threadIdx.x;
    for (int i = t; i < HIDD * HIDD; i += 256) { Wls[i] = Wl[i]; Wrs[i] = Wr[i]; }
    if (t < HIDD) bls[t] = bl[t];
    int j = t & 63;
    int g = t >> 6;                         // 4 nodes per group
    int base = blockIdx.x * UPD_NPB;
    for (int it = 0; it < UPD_NPB; it += 16) {
        __syncthreads();
        {
            int nodebase = base + it;
            const float4* asrc = (const float4*)(g_agg) + (size_t)nodebase * (HIDD / 4);
            const float4* hsrc = (const float4*)(hin)   + (size_t)nodebase * (HIDD / 4);
            float4* ad = (float4*)&as[0][0];
            float4* hd = (float4*)&hs[0][0];
            for (int i = t; i < 16 * HIDD / 4; i += 256) {
                int node = nodebase + i / (HIDD / 4);
                ad[i] = (node < NN) ? asrc[i] : make_float4(0.f, 0.f, 0.f, 0.f);
                hd[i] = (node < NN) ? hsrc[i] : make_float4(0.f, 0.f, 0.f, 0.f);
            }
        }
        __syncthreads();
        int n0 = g * 4;
        float a0 = bls[j], a1 = bls[j], a2 = bls[j], a3 = bls[j];
#pragma unroll 8
        for (int k = 0; k < HIDD; k++) {
            float wl = Wls[k * HIDD + j];
            float wr = Wrs[k * HIDD + j];
            a0 = fmaf(as[n0 + 0][k], wl, fmaf(hs[n0 + 0][k], wr, a0));
            a1 = fmaf(as[n0 + 1][k], wl, fmaf(hs[n0 + 1][k], wr, a1));
            a2 = fmaf(as[n0 + 2][k], wl, fmaf(hs[n0 + 2][k], wr, a2));
            a3 = fmaf(as[n0 + 3][k], wl, fmaf(hs[n0 + 3][k], wr, a3));
        }
        int node = base + it + n0;
        if (node + 0 < NN) hout[(size_t)(node + 0) * HIDD + j] = fmaxf(a0, 0.f);
        if (node + 1 < NN) hout[(size_t)(node + 1) * HIDD + j] = fmaxf(a1, 0.f);
        if (node + 2 < NN) hout[(size_t)(node + 2) * HIDD + j] = fmaxf(a2, 0.f);
        if (node + 3 < NN) hout[(size_t)(node + 3) * HIDD + j] = fmaxf(a3, 0.f);
    }
}

// ---------------- predictor: out = relu([hA,hB]@W1 + b1)@W2 + b2 --------------
__global__ void k_predict(int flip,
                          const int* __restrict__ pair,
                          const float* __restrict__ W1,
                          const float* __restrict__ b1,
                          const float* __restrict__ W2,
                          const float* __restrict__ b2,
                          float* __restrict__ out) {
    const float* __restrict__ h = flip ? g_h2 : g_h;
    __shared__ float W1s[2 * HIDD * HIDD];  // 32 KB
    __shared__ float b1s[HIDD];
    __shared__ float W2s[HIDD];
    __shared__ float zs[8][2][2 * HIDD];    // 8 KB
    int t = threadIdx.x;
    for (int i = t; i < 2 * HIDD * HIDD; i += 256) W1s[i] = W1[i];
    if (t < HIDD) { b1s[t] = b1[t]; W2s[t] = W2[t]; }
    __syncthreads();
    int w = t >> 5, lane = t & 31;
    int p0 = blockIdx.x * 16 + w * 2;       // 2 pairs per warp
#pragma unroll
    for (int q = 0; q < 2; q++) {
        int p = p0 + q;
        if (p < NP) {
            int a  = pair[2 * p];
            int bb = pair[2 * p + 1];
            if ((unsigned)a >= NN)  a  = 0;
            if ((unsigned)bb >= NN) bb = 0;
            zs[w][q][lane]      = h[(size_t)a  * HIDD + lane];
            zs[w][q][lane + 32] = h[(size_t)a  * HIDD + lane + 32];
            zs[w][q][lane + 64] = h[(size_t)bb * HIDD + lane];
            zs[w][q][lane + 96] = h[(size_t)bb * HIDD + lane + 32];
        }
    }
    __syncwarp();
    float a00 = b1s[lane], a01 = b1s[lane + 32];
    float a10 = b1s[lane], a11 = b1s[lane + 32];
#pragma unroll 4
    for (int k = 0; k < 2 * HIDD; k++) {
        float w0 = W1s[k * HIDD + lane];
        float w1 = W1s[k * HIDD + lane + 32];
        float z0 = zs[w][0][k];
        float z1 = zs[w][1][k];
        a00 = fmaf(z0, w0, a00); a01 = fmaf(z0, w1, a01);
        a10 = fmaf(z1, w0, a10); a11 = fmaf(z1, w1, a11);
    }
    float v0 = fmaxf(a00, 0.f) * W2s[lane] + fmaxf(a01, 0.f) * W2s[lane + 32];
    float v1 = fmaxf(a10, 0.f) * W2s[lane] + fmaxf(a11, 0.f) * W2s[lane + 32];
#pragma unroll
    for (int off = 16; off; off >>= 1) {
        v0 += __shfl_xor_sync(0xffffffffu, v0, off);
        v1 += __shfl_xor_sync(0xffffffffu, v1, off);
    }
    if (lane == 0) {
        float bias = b2[0];
        if (p0 + 0 < NP) out[p0 + 0] = v0 + bias;
        if (p0 + 1 < NP) out[p0 + 1] = v1 + bias;
    }
}

// ---------------- launch ------------------------------------------------------
extern "C" void kernel_launch(void* const* d_in, const int* in_sizes, int n_in,
                              void* d_out, int out_size) {
    const float* x    = (const float*)d_in[0];
    const int*   ei   = (const int*)d_in[1];
    const int*   pair = (const int*)d_in[2];
    const float* encW = (const float*)d_in[3];
    const float* encb = (const float*)d_in[4];
    const float* Wl   = (const float*)d_in[5];
    const float* bl   = (const float*)d_in[6];
    const float* Wr   = (const float*)d_in[7];
    const float* W1   = (const float*)d_in[8];
    const float* b1   = (const float*)d_in[9];
    const float* W2   = (const float*)d_in[10];
    const float* b2   = (const float*)d_in[11];
    float* out = (float*)d_out;

    // CSR build (amortized over 3 layers)
    k_zero_cursor<<<(NN + 255) / 256, 256>>>();
    k_hist<<<(NE + 255) / 256, 256>>>(ei);
    k_scan1<<<NB_SCAN, 1024>>>();
    k_scan2<<<1, 128>>>();
    k_scan3<<<NB_SCAN, 1024>>>();
    k_fill<<<(NE + 255) / 256, 256>>>(ei);

    // encoder
    k_encoder<<<(NN + ENC_NPB - 1) / ENC_NPB, 256>>>(x, encW, encb);

    // 3 SAGE layers (ping-pong g_h <-> g_h2)
    int flip = 0;
    for (int i = 0; i < 3; i++) {
        k_aggregate<<<(NN * 32 + 255) / 256, 256>>>(flip);
        k_update<<<(NN + UPD_NPB - 1) / UPD_NPB, 256>>>(flip, Wl + i * HIDD * HIDD,
                                                        bl + i * HIDD, Wr + i * HIDD * HIDD);
        flip ^= 1;
    }
    // after 3 layers (flip toggled 0->1->0->1), final h lives in g_h2
    k_predict<<<(NP + 15) / 16, 256>>>(1, pair, W1, b1, W2, b2, out);
}

// round 3
// speedup vs baseline: 1.2854x; 1.2854x over previous
#include <cuda_runtime.h>

#define NN  100000
#define NE  1250000
#define NP  200000
#define HIDD 64
#define IND 128
#define NB_SCAN 98   // ceil(100000/1024)

// ---------------- scratch (device globals; no allocation allowed) -------------
__device__ __align__(16) float g_h [NN * HIDD];
__device__ __align__(16) float g_h2[NN * HIDD];
__device__ __align__(16) float g_agg[NN * HIDD];
__device__ int   g_rowstart[NN + 1];
__device__ int   g_cursor[NN];
__device__ int   g_col[NE];
__device__ int   g_bsum[NB_SCAN + 8];

// ---------------- CSR build ---------------------------------------------------
__global__ void k_zero_cursor() {
    int i = blockIdx.x * blockDim.x + threadIdx.x;
    if (i < NN) g_cursor[i] = 0;
}

__global__ void k_hist(const int* __restrict__ ei) {
    int e = blockIdx.x * blockDim.x + threadIdx.x;
    if (e < NE) {
        int d = ei[NE + e];
        if ((unsigned)d < NN) atomicAdd(&g_cursor[d], 1);
    }
}

__global__ void k_scan1() {
    __shared__ int s[1024];
    int tid = threadIdx.x;
    int i = blockIdx.x * 1024 + tid;
    int v = (i < NN) ? g_cursor[i] : 0;
    s[tid] = v;
    __syncthreads();
    for (int off = 1; off < 1024; off <<= 1) {
        int t = 0;
        if (tid >= off) t = s[tid - off];
        __syncthreads();
        if (tid >= off) s[tid] += t;
        __syncthreads();
    }
    if (i < NN) g_rowstart[i] = s[tid] - v;
    if (tid == 1023) g_bsum[blockIdx.x] = s[1023];
}

__global__ void k_scan2() {
    __shared__ int s[NB_SCAN];
    int tid = threadIdx.x;
    if (tid < NB_SCAN) s[tid] = g_bsum[tid];
    __syncthreads();
    if (tid == 0) {
        int run = 0;
        for (int b = 0; b < NB_SCAN; b++) { int t = s[b]; s[b] = run; run += t; }
    }
    __syncthreads();
    if (tid < NB_SCAN) g_bsum[tid] = s[tid];
}

__global__ void k_scan3() {
    int i = blockIdx.x * 1024 + threadIdx.x;
    if (i < NN) {
        int r = g_rowstart[i] + g_bsum[blockIdx.x];
        g_rowstart[i] = r;
        g_cursor[i]   = r;
    }
    if (blockIdx.x == 0 && threadIdx.x == 0) g_rowstart[NN] = NE;
}

__global__ void k_fill(const int* __restrict__ ei) {
    int e = blockIdx.x * blockDim.x + threadIdx.x;
    if (e < NE) {
        int s = ei[e];
        int d = ei[NE + e];
        if ((unsigned)d < NN && (unsigned)s < NN) {
            int pos = atomicAdd(&g_cursor[d], 1);
            if ((unsigned)pos < NE) g_col[pos] = s;
        }
    }
}

// =============== encoder: h = relu(x @ W + b), 4x4 register tiles ==============
// smem: WsT[64][132] (W transposed, j-major) + xs[64][132] (node-major, k contig)
#define ENC_SMEM_BYTES (2 * 64 * 132 * 4)
__global__ __launch_bounds__(256) void k_encoder(const float* __restrict__ x,
                                                 const float* __restrict__ W,
                                                 const float* __restrict__ b) {
    extern __shared__ float sm[];
    float* WsT = sm;             // [64][132]
    float* xs  = sm + 64 * 132;  // [64][132]
    __shared__ float bs[64];
    int t = threadIdx.x;
    if (t < 64) bs[t] = b[t];
    // transpose W [128][64] -> WsT[j][k]
    const float4* W4 = (const float4*)W;
    for (int idx = t; idx < 128 * 16; idx += 256) {
        int kk = idx >> 4;
        int j0 = (idx & 15) * 4;
        float4 v = W4[idx];
        WsT[(j0 + 0) * 132 + kk] = v.x;
        WsT[(j0 + 1) * 132 + kk] = v.y;
        WsT[(j0 + 2) * 132 + kk] = v.z;
        WsT[(j0 + 3) * 132 + kk] = v.w;
    }
    int jg = t & 15, ng = t >> 4;
    int base0 = blockIdx.x * 128;
    for (int c = 0; c < 2; c++) {
        int base = base0 + c * 64;
        __syncthreads();
        for (int idx = t; idx < 64 * 32; idx += 256) {
            int n = idx >> 5, kq = idx & 31;
            int node = base + n;
            float4 v = (node < NN) ? ((const float4*)x)[(size_t)node * 32 + kq]
                                   : make_float4(0.f, 0.f, 0.f, 0.f);
            *(float4*)&xs[n * 132 + kq * 4] = v;
        }
        __syncthreads();
        float acc[4][4];
#pragma unroll
        for (int j = 0; j < 4; j++) {
            float bb = bs[jg + 16 * j];
            acc[0][j] = bb; acc[1][j] = bb; acc[2][j] = bb; acc[3][j] = bb;
        }
#pragma unroll 4
        for (int k = 0; k < 128; k += 4) {
            float4 xv[4], wv[4];
#pragma unroll
            for (int i = 0; i < 4; i++) xv[i] = *(const float4*)&xs[(ng + 16 * i) * 132 + k];
#pragma unroll
            for (int i = 0; i < 4; i++) wv[i] = *(const float4*)&WsT[(jg + 16 * i) * 132 + k];
#pragma unroll
            for (int n = 0; n < 4; n++)
#pragma unroll
                for (int j = 0; j < 4; j++) {
                    acc[n][j] = fmaf(xv[n].x, wv[j].x, acc[n][j]);
                    acc[n][j] = fmaf(xv[n].y, wv[j].y, acc[n][j]);
                    acc[n][j] = fmaf(xv[n].z, wv[j].z, acc[n][j]);
                    acc[n][j] = fmaf(xv[n].w, wv[j].w, acc[n][j]);
                }
        }
#pragma unroll
        for (int n = 0; n < 4; n++) {
            int node = base + ng + 16 * n;
            if (node < NN) {
#pragma unroll
                for (int j = 0; j < 4; j++)
                    g_h[(size_t)node * 64 + jg + 16 * j] = fmaxf(acc[n][j], 0.f);
            }
        }
    }
}

// ---------------- mean aggregation (CSR gather; warp per node, float2) --------
__global__ void k_aggregate(int flip) {
    const float2* __restrict__ hin = (const float2*)(flip ? g_h2 : g_h);
    int warp = (blockIdx.x * blockDim.x + threadIdx.x) >> 5;
    int lane = threadIdx.x & 31;
    if (warp >= NN) return;
    int s0 = g_rowstart[warp];
    int s1 = g_rowstart[warp + 1];
    float ax = 0.f, ay = 0.f;
    int e = s0;
    for (; e + 1 < s1; e += 2) {
        float2 v0 = hin[(size_t)g_col[e] * 32 + lane];
        float2 v1 = hin[(size_t)g_col[e + 1] * 32 + lane];
        ax += v0.x + v1.x;
        ay += v0.y + v1.y;
    }
    if (e < s1) {
        float2 v0 = hin[(size_t)g_col[e] * 32 + lane];
        ax += v0.x; ay += v0.y;
    }
    float inv = (s1 > s0) ? 1.0f / (float)(s1 - s0) : 0.f;
    float2 r; r.x = ax * inv; r.y = ay * inv;
    ((float2*)g_agg)[(size_t)warp * 32 + lane] = r;
}

// =============== layer update: h' = relu(agg@Wl + bl + h@Wr), 4x4 tiles =======
// smem: WlT[64][68] + WrT[64][68] + as[64][68] + hs[64][68]
#define UPD_SMEM_BYTES (4 * 64 * 68 * 4)
__global__ __launch_bounds__(256) void k_update(int flip,
                                                const float* __restrict__ Wl,
                                                const float* __restrict__ bl,
                                                const float* __restrict__ Wr) {
    const float* __restrict__ hin = flip ? g_h2 : g_h;
    float* __restrict__ hout      = flip ? g_h  : g_h2;
    extern __shared__ float sm[];
    float* WlT = sm;
    float* WrT = sm + 64 * 68;
    float* as  = sm + 2 * 64 * 68;
    float* hs  = sm + 3 * 64 * 68;
    __shared__ float bs[64];
    int t = threadIdx.x;
    if (t < 64) bs[t] = bl[t];
    // transpose Wl, Wr ([64][64] each -> [j][k])
    const float4* Wl4 = (const float4*)Wl;
    const float4* Wr4 = (const float4*)Wr;
    for (int idx = t; idx < 2 * 64 * 16; idx += 256) {
        int m = idx >> 10;            // 0 = Wl, 1 = Wr
        int r = idx & 1023;
        int kk = r >> 4;
        int j0 = (r & 15) * 4;
        float4 v = m ? Wr4[r] : Wl4[r];
        float* dst = m ? WrT : WlT;
        dst[(j0 + 0) * 68 + kk] = v.x;
        dst[(j0 + 1) * 68 + kk] = v.y;
        dst[(j0 + 2) * 68 + kk] = v.z;
        dst[(j0 + 3) * 68 + kk] = v.w;
    }
    int jg = t & 15, ng = t >> 4;
    int base0 = blockIdx.x * 128;
    for (int c = 0; c < 2; c++) {
        int base = base0 + c * 64;
        __syncthreads();
        for (int idx = t; idx < 2 * 64 * 16; idx += 256) {
            int m = idx >> 10;            // 0 = agg, 1 = h
            int r = idx & 1023;
            int n = r >> 4, kq = r & 15;
            int node = base + n;
            const float4* src = m ? (const float4*)hin : (const float4*)g_agg;
            float4 v = (node < NN) ? src[(size_t)node * 16 + kq]
                                   : make_float4(0.f, 0.f, 0.f, 0.f);
            float* dst = m ? hs : as;
            *(float4*)&dst[n * 68 + kq * 4] = v;
        }
        __syncthreads();
        float acc[4][4];
#pragma unroll
        for (int j = 0; j < 4; j++) {
            float bb = bs[jg + 16 * j];
            acc[0][j] = bb; acc[1][j] = bb; acc[2][j] = bb; acc[3][j] = bb;
        }
        // phase 1: agg @ Wl
#pragma unroll 4
        for (int k = 0; k < 64; k += 4) {
            float4 xv[4], wv[4];
#pragma unroll
            for (int i = 0; i < 4; i++) xv[i] = *(const float4*)&as[(ng + 16 * i) * 68 + k];
#pragma unroll
            for (int i = 0; i < 4; i++) wv[i] = *(const float4*)&WlT[(jg + 16 * i) * 68 + k];
#pragma unroll
            for (int n = 0; n < 4; n++)
#pragma unroll
                for (int j = 0; j < 4; j++) {
                    acc[n][j] = fmaf(xv[n].x, wv[j].x, acc[n][j]);
                    acc[n][j] = fmaf(xv[n].y, wv[j].y, acc[n][j]);
                    acc[n][j] = fmaf(xv[n].z, wv[j].z, acc[n][j]);
                    acc[n][j] = fmaf(xv[n].w, wv[j].w, acc[n][j]);
                }
        }
        // phase 2: h @ Wr
#pragma unroll 4
        for (int k = 0; k < 64; k += 4) {
            float4 xv[4], wv[4];
#pragma unroll
            for (int i = 0; i < 4; i++) xv[i] = *(const float4*)&hs[(ng + 16 * i) * 68 + k];
#pragma unroll
            for (int i = 0; i < 4; i++) wv[i] = *(const float4*)&WrT[(jg + 16 * i) * 68 + k];
#pragma unroll
            for (int n = 0; n < 4; n++)
#pragma unroll
                for (int j = 0; j < 4; j++) {
                    acc[n][j] = fmaf(xv[n].x, wv[j].x, acc[n][j]);
                    acc[n][j] = fmaf(xv[n].y, wv[j].y, acc[n][j]);
                    acc[n][j] = fmaf(xv[n].z, wv[j].z, acc[n][j]);
                    acc[n][j] = fmaf(xv[n].w, wv[j].w, acc[n][j]);
                }
        }
#pragma unroll
        for (int n = 0; n < 4; n++) {
            int node = base + ng + 16 * n;
            if (node < NN) {
#pragma unroll
                for (int j = 0; j < 4; j++)
                    hout[(size_t)node * 64 + jg + 16 * j] = fmaxf(acc[n][j], 0.f);
            }
        }
    }
}

// =============== predictor: relu([hA,hB]@W1+b1)@W2+b2, 4x4 tiles ==============
// smem: W1T[64][132] + zs[64][132]
#define PRED_SMEM_BYTES (2 * 64 * 132 * 4)
__global__ __launch_bounds__(256) void k_predict(int flip,
                                                 const int* __restrict__ pair,
                                                 const float* __restrict__ W1,
                                                 const float* __restrict__ b1,
                                                 const float* __restrict__ W2,
                                                 const float* __restrict__ b2,
                                                 float* __restrict__ out) {
    const float4* __restrict__ h4 = (const float4*)(flip ? g_h2 : g_h);
    extern __shared__ float sm[];
    float* W1T = sm;             // [64][132]
    float* zs  = sm + 64 * 132;  // [64][132]
    __shared__ int   pidx[128];
    __shared__ float b1s[64], W2s[64];
    int t = threadIdx.x;
    if (t < 64) { b1s[t] = b1[t]; W2s[t] = W2[t]; }
    float b2v = b2[0];
    // transpose W1 [128][64] -> W1T[j][k]
    const float4* W14 = (const float4*)W1;
    for (int idx = t; idx < 128 * 16; idx += 256) {
        int kk = idx >> 4;
        int j0 = (idx & 15) * 4;
        float4 v = W14[idx];
        W1T[(j0 + 0) * 132 + kk] = v.x;
        W1T[(j0 + 1) * 132 + kk] = v.y;
        W1T[(j0 + 2) * 132 + kk] = v.z;
        W1T[(j0 + 3) * 132 + kk] = v.w;
    }
    int jg = t & 15, ng = t >> 4;
    int lane = t & 31;
    int base0 = blockIdx.x * 128;
    for (int c = 0; c < 2; c++) {
        int base = base0 + c * 64;
        __syncthreads();
        if (t < 128) {
            int p = base + (t >> 1);
            int v = (p < NP) ? pair[p * 2 + (t & 1)] : 0;
            if ((unsigned)v >= NN) v = 0;
            pidx[t] = v;
        }
        __syncthreads();
        // stage z: [hA (k 0..63) | hB (k 64..127)]
        for (int idx = t; idx < 64 * 32; idx += 256) {
            int p = idx >> 5, q = idx & 31;
            int src = pidx[p * 2 + (q >> 4)];
            float4 v = h4[(size_t)src * 16 + (q & 15)];
            *(float4*)&zs[p * 132 + q * 4] = v;
        }
        __syncthreads();
        float acc[4][4];
#pragma unroll
        for (int j = 0; j < 4; j++) {
            float bb = b1s[jg + 16 * j];
            acc[0][j] = bb; acc[1][j] = bb; acc[2][j] = bb; acc[3][j] = bb;
        }
#pragma unroll 4
        for (int k = 0; k < 128; k += 4) {
            float4 zv[4], wv[4];
#pragma unroll
            for (int i = 0; i < 4; i++) zv[i] = *(const float4*)&zs[(ng + 16 * i) * 132 + k];
#pragma unroll
            for (int i = 0; i < 4; i++) wv[i] = *(const float4*)&W1T[(jg + 16 * i) * 132 + k];
#pragma unroll
            for (int n = 0; n < 4; n++)
#pragma unroll
                for (int j = 0; j < 4; j++) {
                    acc[n][j] = fmaf(zv[n].x, wv[j].x, acc[n][j]);
                    acc[n][j] = fmaf(zv[n].y, wv[j].y, acc[n][j]);
                    acc[n][j] = fmaf(zv[n].z, wv[j].z, acc[n][j]);
                    acc[n][j] = fmaf(zv[n].w, wv[j].w, acc[n][j]);
                }
        }
        // second MLP layer: dot(relu(.), W2) with reduce over the 16 jg lanes
        float s[4];
#pragma unroll
        for (int n = 0; n < 4; n++) {
            s[n] = 0.f;
#pragma unroll
            for (int j = 0; j < 4; j++)
                s[n] = fmaf(fmaxf(acc[n][j], 0.f), W2s[jg + 16 * j], s[n]);
        }
#pragma unroll
        for (int off = 8; off; off >>= 1) {
#pragma unroll
            for (int n = 0; n < 4; n++)
                s[n] += __shfl_xor_sync(0xffffffffu, s[n], off);
        }
        if (jg == 0) {
#pragma unroll
            for (int n = 0; n < 4; n++) {
                int p = base + ng + 16 * n;
                if (p < NP) out[p] = s[n] + b2v;
            }
        }
        (void)lane;
    }
}

// ---------------- launch ------------------------------------------------------
extern "C" void kernel_launch(void* const* d_in, const int* in_sizes, int n_in,
                              void* d_out, int out_size) {
    const float* x    = (const float*)d_in[0];
    const int*   ei   = (const int*)d_in[1];
    const int*   pair = (const int*)d_in[2];
    const float* encW = (const float*)d_in[3];
    const float* encb = (const float*)d_in[4];
    const float* Wl   = (const float*)d_in[5];
    const float* bl   = (const float*)d_in[6];
    const float* Wr   = (const float*)d_in[7];
    const float* W1   = (const float*)d_in[8];
    const float* b1   = (const float*)d_in[9];
    const float* W2   = (const float*)d_in[10];
    const float* b2   = (const float*)d_in[11];
    float* out = (float*)d_out;

    cudaFuncSetAttribute(k_encoder, cudaFuncAttributeMaxDynamicSharedMemorySize, ENC_SMEM_BYTES);
    cudaFuncSetAttribute(k_update,  cudaFuncAttributeMaxDynamicSharedMemorySize, UPD_SMEM_BYTES);
    cudaFuncSetAttribute(k_predict, cudaFuncAttributeMaxDynamicSharedMemorySize, PRED_SMEM_BYTES);

    // CSR build
    k_zero_cursor<<<(NN + 255) / 256, 256>>>();
    k_hist<<<(NE + 255) / 256, 256>>>(ei);
    k_scan1<<<NB_SCAN, 1024>>>();
    k_scan2<<<1, 128>>>();
    k_scan3<<<NB_SCAN, 1024>>>();
    k_fill<<<(NE + 255) / 256, 256>>>(ei);

    // encoder
    k_encoder<<<(NN + 127) / 128, 256, ENC_SMEM_BYTES>>>(x, encW, encb);

    // 3 SAGE layers (ping-pong g_h <-> g_h2)
    int flip = 0;
    for (int i = 0; i < 3; i++) {
        k_aggregate<<<(NN * 32 + 255) / 256, 256>>>(flip);
        k_update<<<(NN + 127) / 128, 256, UPD_SMEM_BYTES>>>(flip, Wl + i * HIDD * HIDD,
                                                            bl + i * HIDD, Wr + i * HIDD * HIDD);
        flip ^= 1;
    }
    // final h lives in g_h2
    k_predict<<<(NP + 127) / 128, 256, PRED_SMEM_BYTES>>>(1, pair, W1, b1, W2, b2, out);
}

// round 4
// speedup vs baseline: 1.3298x; 1.0345x over previous
#include <cuda_runtime.h>

#define NN  100000
#define NE  1250000
#define NP  200000
#define HIDD 64
#define IND 128
#define NB_SCAN 98   // ceil(100000/1024)

// packed f32x2 FMA: d = a*b + c elementwise on (lo,hi) -> SASS FFMA2
#define FMA2(d, a, b, c) \
    asm("fma.rn.f32x2 %0, %1, %2, %3;" : "=l"(d) : "l"(a), "l"(b), "l"(c))

__device__ __forceinline__ float unpack_sum(unsigned long long p) {
    float2 f;
    asm("mov.b64 {%0, %1}, %2;" : "=f"(f.x), "=f"(f.y) : "l"(p));
    return f.x + f.y;
}

// ---------------- scratch (device globals; no allocation allowed) -------------
__device__ __align__(16) float g_h [NN * HIDD];
__device__ __align__(16) float g_h2[NN * HIDD];
__device__ __align__(16) float g_agg[NN * HIDD];
__device__ int   g_rowstart[NN + 1];
__device__ int   g_cursor[NN];
__device__ int   g_col[NE];
__device__ int   g_bsum[NB_SCAN + 8];

// ---------------- CSR build ---------------------------------------------------
__global__ void k_zero_cursor() {
    int i = blockIdx.x * blockDim.x + threadIdx.x;
    if (i < NN) g_cursor[i] = 0;
}

__global__ void k_hist(const int* __restrict__ ei) {
    int e = blockIdx.x * blockDim.x + threadIdx.x;
    if (e < NE) {
        int d = ei[NE + e];
        if ((unsigned)d < NN) atomicAdd(&g_cursor[d], 1);
    }
}

__global__ void k_scan1() {
    __shared__ int s[1024];
    int tid = threadIdx.x;
    int i = blockIdx.x * 1024 + tid;
    int v = (i < NN) ? g_cursor[i] : 0;
    s[tid] = v;
    __syncthreads();
    for (int off = 1; off < 1024; off <<= 1) {
        int t = 0;
        if (tid >= off) t = s[tid - off];
        __syncthreads();
        if (tid >= off) s[tid] += t;
        __syncthreads();
    }
    if (i < NN) g_rowstart[i] = s[tid] - v;
    if (tid == 1023) g_bsum[blockIdx.x] = s[1023];
}

__global__ void k_scan2() {
    __shared__ int s[NB_SCAN];
    int tid = threadIdx.x;
    if (tid < NB_SCAN) s[tid] = g_bsum[tid];
    __syncthreads();
    if (tid == 0) {
        int run = 0;
        for (int b = 0; b < NB_SCAN; b++) { int t = s[b]; s[b] = run; run += t; }
    }
    __syncthreads();
    if (tid < NB_SCAN) g_bsum[tid] = s[tid];
}

__global__ void k_scan3() {
    int i = blockIdx.x * 1024 + threadIdx.x;
    if (i < NN) {
        int r = g_rowstart[i] + g_bsum[blockIdx.x];
        g_rowstart[i] = r;
        g_cursor[i]   = r;
    }
    if (blockIdx.x == 0 && threadIdx.x == 0) g_rowstart[NN] = NE;
}

__global__ void k_fill(const int* __restrict__ ei) {
    int e = blockIdx.x * blockDim.x + threadIdx.x;
    if (e < NE) {
        int s = ei[e];
        int d = ei[NE + e];
        if ((unsigned)d < NN && (unsigned)s < NN) {
            int pos = atomicAdd(&g_cursor[d], 1);
            if ((unsigned)pos < NE) g_col[pos] = s;
        }
    }
}

// =============== encoder: h = relu(x @ W + b), 4x4 tiles, FFMA2 ===============
#define ENC_SMEM_BYTES (2 * 64 * 132 * 4)
__global__ __launch_bounds__(256) void k_encoder(const float* __restrict__ x,
                                                 const float* __restrict__ W,
                                                 const float* __restrict__ b) {
    extern __shared__ float sm[];
    float* WsT = sm;             // [64][132]  (W transposed, j-major, k contig)
    float* xs  = sm + 64 * 132;  // [64][132]  (node-major, k contig)
    __shared__ float bs[64];
    int t = threadIdx.x;
    if (t < 64) bs[t] = b[t];
    const float4* W4 = (const float4*)W;
    for (int idx = t; idx < 128 * 16; idx += 256) {
        int kk = idx >> 4;
        int j0 = (idx & 15) * 4;
        float4 v = W4[idx];
        WsT[(j0 + 0) * 132 + kk] = v.x;
        WsT[(j0 + 1) * 132 + kk] = v.y;
        WsT[(j0 + 2) * 132 + kk] = v.z;
        WsT[(j0 + 3) * 132 + kk] = v.w;
    }
    int jg = t & 15, ng = t >> 4;
    int base0 = blockIdx.x * 128;
    for (int c = 0; c < 2; c++) {
        int base = base0 + c * 64;
        __syncthreads();
        for (int idx = t; idx < 64 * 32; idx += 256) {
            int n = idx >> 5, kq = idx & 31;
            int node = base + n;
            float4 v = (node < NN) ? ((const float4*)x)[(size_t)node * 32 + kq]
                                   : make_float4(0.f, 0.f, 0.f, 0.f);
            *(float4*)&xs[n * 132 + kq * 4] = v;
        }
        __syncthreads();
        unsigned long long acc[4][4];
#pragma unroll
        for (int n = 0; n < 4; n++)
#pragma unroll
            for (int j = 0; j < 4; j++) acc[n][j] = 0ull;
#pragma unroll 4
        for (int k = 0; k < 128; k += 4) {
            ulonglong2 xv[4], wv[4];
#pragma unroll
            for (int i = 0; i < 4; i++) xv[i] = *(const ulonglong2*)&xs[(ng + 16 * i) * 132 + k];
#pragma unroll
            for (int i = 0; i < 4; i++) wv[i] = *(const ulonglong2*)&WsT[(jg + 16 * i) * 132 + k];
#pragma unroll
            for (int n = 0; n < 4; n++)
#pragma unroll
                for (int j = 0; j < 4; j++) {
                    FMA2(acc[n][j], xv[n].x, wv[j].x, acc[n][j]);
                    FMA2(acc[n][j], xv[n].y, wv[j].y, acc[n][j]);
                }
        }
#pragma unroll
        for (int n = 0; n < 4; n++) {
            int node = base + ng + 16 * n;
            if (node < NN) {
#pragma unroll
                for (int j = 0; j < 4; j++) {
                    float v = unpack_sum(acc[n][j]) + bs[jg + 16 * j];
                    g_h[(size_t)node * 64 + jg + 16 * j] = fmaxf(v, 0.f);
                }
            }
        }
    }
}

// ---------------- mean aggregation (CSR gather; warp per node, float2) --------
__global__ void k_aggregate(int flip) {
    const float2* __restrict__ hin = (const float2*)(flip ? g_h2 : g_h);
    int warp = (blockIdx.x * blockDim.x + threadIdx.x) >> 5;
    int lane = threadIdx.x & 31;
    if (warp >= NN) return;
    int s0 = g_rowstart[warp];
    int s1 = g_rowstart[warp + 1];
    float ax = 0.f, ay = 0.f;
    int e = s0;
    for (; e + 3 < s1; e += 4) {
        int c0 = g_col[e], c1 = g_col[e + 1], c2 = g_col[e + 2], c3 = g_col[e + 3];
        float2 v0 = hin[(size_t)c0 * 32 + lane];
        float2 v1 = hin[(size_t)c1 * 32 + lane];
        float2 v2 = hin[(size_t)c2 * 32 + lane];
        float2 v3 = hin[(size_t)c3 * 32 + lane];
        ax += (v0.x + v1.x) + (v2.x + v3.x);
        ay += (v0.y + v1.y) + (v2.y + v3.y);
    }
    for (; e < s1; e++) {
        float2 v0 = hin[(size_t)g_col[e] * 32 + lane];
        ax += v0.x; ay += v0.y;
    }
    float inv = (s1 > s0) ? 1.0f / (float)(s1 - s0) : 0.f;
    float2 r; r.x = ax * inv; r.y = ay * inv;
    ((float2*)g_agg)[(size_t)warp * 32 + lane] = r;
}

// =============== layer update: relu(agg@Wl + bl + h@Wr), 4x4 tiles, FFMA2 =====
#define UPD_SMEM_BYTES (4 * 64 * 68 * 4)
__global__ __launch_bounds__(256) void k_update(int flip,
                                                const float* __restrict__ Wl,
                                                const float* __restrict__ bl,
                                                const float* __restrict__ Wr) {
    const float* __restrict__ hin = flip ? g_h2 : g_h;
    float* __restrict__ hout      = flip ? g_h  : g_h2;
    extern __shared__ float sm[];
    float* WlT = sm;
    float* WrT = sm + 64 * 68;
    float* as  = sm + 2 * 64 * 68;
    float* hs  = sm + 3 * 64 * 68;
    __shared__ float bs[64];
    int t = threadIdx.x;
    if (t < 64) bs[t] = bl[t];
    const float4* Wl4 = (const float4*)Wl;
    const float4* Wr4 = (const float4*)Wr;
    for (int idx = t; idx < 2 * 64 * 16; idx += 256) {
        int m = idx >> 10;
        int r = idx & 1023;
        int kk = r >> 4;
        int j0 = (r & 15) * 4;
        float4 v = m ? Wr4[r] : Wl4[r];
        float* dst = m ? WrT : WlT;
        dst[(j0 + 0) * 68 + kk] = v.x;
        dst[(j0 + 1) * 68 + kk] = v.y;
        dst[(j0 + 2) * 68 + kk] = v.z;
        dst[(j0 + 3) * 68 + kk] = v.w;
    }
    int jg = t & 15, ng = t >> 4;
    int base0 = blockIdx.x * 128;
    for (int c = 0; c < 2; c++) {
        int base = base0 + c * 64;
        __syncthreads();
        for (int idx = t; idx < 2 * 64 * 16; idx += 256) {
            int m = idx >> 10;
            int r = idx & 1023;
            int n = r >> 4, kq = r & 15;
            int node = base + n;
            const float4* src = m ? (const float4*)hin : (const float4*)g_agg;
            float4 v = (node < NN) ? src[(size_t)node * 16 + kq]
                                   : make_float4(0.f, 0.f, 0.f, 0.f);
            float* dst = m ? hs : as;
            *(float4*)&dst[n * 68 + kq * 4] = v;
        }
        __syncthreads();
        unsigned long long acc[4][4];
#pragma unroll
        for (int n = 0; n < 4; n++)
#pragma unroll
            for (int j = 0; j < 4; j++) acc[n][j] = 0ull;
        // phase 1: agg @ Wl
#pragma unroll 4
        for (int k = 0; k < 64; k += 4) {
            ulonglong2 xv[4], wv[4];
#pragma unroll
            for (int i = 0; i < 4; i++) xv[i] = *(const ulonglong2*)&as[(ng + 16 * i) * 68 + k];
#pragma unroll
            for (int i = 0; i < 4; i++) wv[i] = *(const ulonglong2*)&WlT[(jg + 16 * i) * 68 + k];
#pragma unroll
            for (int n = 0; n < 4; n++)
#pragma unroll
                for (int j = 0; j < 4; j++) {
                    FMA2(acc[n][j], xv[n].x, wv[j].x, acc[n][j]);
                    FMA2(acc[n][j], xv[n].y, wv[j].y, acc[n][j]);
                }
        }
        // phase 2: h @ Wr
#pragma unroll 4
        for (int k = 0; k < 64; k += 4) {
            ulonglong2 xv[4], wv[4];
#pragma unroll
            for (int i = 0; i < 4; i++) xv[i] = *(const ulonglong2*)&hs[(ng + 16 * i) * 68 + k];
#pragma unroll
            for (int i = 0; i < 4; i++) wv[i] = *(const ulonglong2*)&WrT[(jg + 16 * i) * 68 + k];
#pragma unroll
            for (int n = 0; n < 4; n++)
#pragma unroll
                for (int j = 0; j < 4; j++) {
                    FMA2(acc[n][j], xv[n].x, wv[j].x, acc[n][j]);
                    FMA2(acc[n][j], xv[n].y, wv[j].y, acc[n][j]);
                }
        }
#pragma unroll
        for (int n = 0; n < 4; n++) {
            int node = base + ng + 16 * n;
            if (node < NN) {
#pragma unroll
                for (int j = 0; j < 4; j++) {
                    float v = unpack_sum(acc[n][j]) + bs[jg + 16 * j];
                    hout[(size_t)node * 64 + jg + 16 * j] = fmaxf(v, 0.f);
                }
            }
        }
    }
}

// =============== predictor: relu([hA,hB]@W1+b1)@W2+b2, 4x4 tiles, FFMA2 =======
#define PRED_SMEM_BYTES (2 * 64 * 132 * 4)
__global__ __launch_bounds__(256) void k_predict(int flip,
                                                 const int* __restrict__ pair,
                                                 const float* __restrict__ W1,
                                                 const float* __restrict__ b1,
                                                 const float* __restrict__ W2,
                                                 const float* __restrict__ b2,
                                                 float* __restrict__ out) {
    const float4* __restrict__ h4 = (const float4*)(flip ? g_h2 : g_h);
    extern __shared__ float sm[];
    float* W1T = sm;             // [64][132]
    float* zs  = sm + 64 * 132;  // [64][132]
    __shared__ int   pidx[128];
    __shared__ float b1s[64], W2s[64];
    int t = threadIdx.x;
    if (t < 64) { b1s[t] = b1[t]; W2s[t] = W2[t]; }
    float b2v = b2[0];
    const float4* W14 = (const float4*)W1;
    for (int idx = t; idx < 128 * 16; idx += 256) {
        int kk = idx >> 4;
        int j0 = (idx & 15) * 4;
        float4 v = W14[idx];
        W1T[(j0 + 0) * 132 + kk] = v.x;
        W1T[(j0 + 1) * 132 + kk] = v.y;
        W1T[(j0 + 2) * 132 + kk] = v.z;
        W1T[(j0 + 3) * 132 + kk] = v.w;
    }
    int jg = t & 15, ng = t >> 4;
    int base0 = blockIdx.x * 128;
    for (int c = 0; c < 2; c++) {
        int base = base0 + c * 64;
        __syncthreads();
        if (t < 128) {
            int p = base + (t >> 1);
            int v = (p < NP) ? pair[p * 2 + (t & 1)] : 0;
            if ((unsigned)v >= NN) v = 0;
            pidx[t] = v;
        }
        __syncthreads();
        for (int idx = t; idx < 64 * 32; idx += 256) {
            int p = idx >> 5, q = idx & 31;
            int src = pidx[p * 2 + (q >> 4)];
            float4 v = h4[(size_t)src * 16 + (q & 15)];
            *(float4*)&zs[p * 132 + q * 4] = v;
        }
        __syncthreads();
        unsigned long long acc[4][4];
#pragma unroll
        for (int n = 0; n < 4; n++)
#pragma unroll
            for (int j = 0; j < 4; j++) acc[n][j] = 0ull;
#pragma unroll 4
        for (int k = 0; k < 128; k += 4) {
            ulonglong2 zv[4], wv[4];
#pragma unroll
            for (int i = 0; i < 4; i++) zv[i] = *(const ulonglong2*)&zs[(ng + 16 * i) * 132 + k];
#pragma unroll
            for (int i = 0; i < 4; i++) wv[i] = *(const ulonglong2*)&W1T[(jg + 16 * i) * 132 + k];
#pragma unroll
            for (int n = 0; n < 4; n++)
#pragma unroll
                for (int j = 0; j < 4; j++) {
                    FMA2(acc[n][j], zv[n].x, wv[j].x, acc[n][j]);
                    FMA2(acc[n][j], zv[n].y, wv[j].y, acc[n][j]);
                }
        }
        float s[4];
#pragma unroll
        for (int n = 0; n < 4; n++) {
            s[n] = 0.f;
#pragma unroll
            for (int j = 0; j < 4; j++) {
                float v = unpack_sum(acc[n][j]) + b1s[jg + 16 * j];
                s[n] = fmaf(fmaxf(v, 0.f), W2s[jg + 16 * j], s[n]);
            }
        }
#pragma unroll
        for (int off = 8; off; off >>= 1) {
#pragma unroll
            for (int n = 0; n < 4; n++)
                s[n] += __shfl_xor_sync(0xffffffffu, s[n], off);
        }
        if (jg == 0) {
#pragma unroll
            for (int n = 0; n < 4; n++) {
                int p = base + ng + 16 * n;
                if (p < NP) out[p] = s[n] + b2v;
            }
        }
    }
}

// ---------------- launch ------------------------------------------------------
extern "C" void kernel_launch(void* const* d_in, const int* in_sizes, int n_in,
                              void* d_out, int out_size) {
    const float* x    = (const float*)d_in[0];
    const int*   ei   = (const int*)d_in[1];
    const int*   pair = (const int*)d_in[2];
    const float* encW = (const float*)d_in[3];
    const float* encb = (const float*)d_in[4];
    const float* Wl   = (const float*)d_in[5];
    const float* bl   = (const float*)d_in[6];
    const float* Wr   = (const float*)d_in[7];
    const float* W1   = (const float*)d_in[8];
    const float* b1   = (const float*)d_in[9];
    const float* W2   = (const float*)d_in[10];
    const float* b2   = (const float*)d_in[11];
    float* out = (float*)d_out;

    cudaFuncSetAttribute(k_encoder, cudaFuncAttributeMaxDynamicSharedMemorySize, ENC_SMEM_BYTES);
    cudaFuncSetAttribute(k_update,  cudaFuncAttributeMaxDynamicSharedMemorySize, UPD_SMEM_BYTES);
    cudaFuncSetAttribute(k_predict, cudaFuncAttributeMaxDynamicSharedMemorySize, PRED_SMEM_BYTES);

    // CSR build
    k_zero_cursor<<<(NN + 255) / 256, 256>>>();
    k_hist<<<(NE + 255) / 256, 256>>>(ei);
    k_scan1<<<NB_SCAN, 1024>>>();
    k_scan2<<<1, 128>>>();
    k_scan3<<<NB_SCAN, 1024>>>();
    k_fill<<<(NE + 255) / 256, 256>>>(ei);

    // encoder
    k_encoder<<<(NN + 127) / 128, 256, ENC_SMEM_BYTES>>>(x, encW, encb);

    // 3 SAGE layers (ping-pong g_h <-> g_h2)
    int flip = 0;
    for (int i = 0; i < 3; i++) {
        k_aggregate<<<(NN * 32 + 255) / 256, 256>>>(flip);
        k_update<<<(NN + 127) / 128, 256, UPD_SMEM_BYTES>>>(flip, Wl + i * HIDD * HIDD,
                                                            bl + i * HIDD, Wr + i * HIDD * HIDD);
        flip ^= 1;
    }
    // final h lives in g_h2
    k_predict<<<(NP + 127) / 128, 256, PRED_SMEM_BYTES>>>(1, pair, W1, b1, W2, b2, out);
}